// round 12
// baseline (speedup 1.0000x reference)
#include <cuda_runtime.h>
#include <cuda_bf16.h>
#include <cstdint>

// Per-token-group (G=128) dynamic fp8-range quantization.
// x: [M, N] fp32 (bf16-rounded values upcast by harness).
// y = clip(x * 448/amax, +-448) fp32; scale = max(amax,1e-4)/448 per group.
// d_out layout: [y (M*N) || scale (M*N/128)] fp32.
//
// Persistent grid (152 SM x 8 CTA resident) + software-pipelined prefetch:
// each warp grid-strides over group-pairs, issuing the next pair's loads
// before processing the current pair. Removes the ~28 wave transitions of
// the flat launch and keeps 2 LDG.128 permanently in flight per warp.

#define GROUP_SIZE 128
#define FP8_MAX 448.0f
#define AMAX_FLOOR 1e-4f

__device__ float g_scale_scratch[1 << 20];  // fallback, never used in practice

__device__ __forceinline__ float max4abs(float4 v) {
    return fmaxf(fmaxf(fabsf(v.x), fabsf(v.y)), fmaxf(fabsf(v.z), fabsf(v.w)));
}

__device__ __forceinline__ float4 scale4(float4 v, float s) {
    float4 o;
    o.x = fminf(fmaxf(v.x * s, -FP8_MAX), FP8_MAX);
    o.y = fminf(fmaxf(v.y * s, -FP8_MAX), FP8_MAX);
    o.z = fminf(fmaxf(v.z * s, -FP8_MAX), FP8_MAX);
    o.w = fminf(fmaxf(v.w * s, -FP8_MAX), FP8_MAX);
    return o;
}

__global__ void __launch_bounds__(256, 8) quant_fp8_group_kernel(
    const float4* __restrict__ x4,
    float4* __restrict__ y4,
    float* __restrict__ scale,
    int num_groups)
{
    const int lane = threadIdx.x & 31;
    const int W = gridDim.x * 8;                       // total warps in grid
    const int num_pairs = (num_groups + 1) >> 1;

    int p = blockIdx.x * 8 + (threadIdx.x >> 5);       // this warp's first pair
    if (p >= num_pairs) return;

    size_t base = (size_t)p * 64 + lane;               // float4 units
    float4 a = x4[base];
    bool hasb = (2 * p + 1) < num_groups;
    float4 b = hasb ? x4[base + 32] : a;               // safe duplicate on odd tail

    while (true) {
        // ---- prefetch next pair (issues before any dependency on a/b) ----
        const int pn = p + W;
        const bool more = pn < num_pairs;
        const size_t nbase = (size_t)pn * 64 + lane;
        float4 an, bn;
        bool hasbn = false;
        if (more) {
            an = x4[nbase];
            hasbn = (2 * pn + 1) < num_groups;
            bn = hasbn ? x4[nbase + 32] : an;
        }

        // ---- process current pair ----
        unsigned ra = __reduce_max_sync(0xffffffffu, __float_as_uint(max4abs(a)));
        unsigned rb = __reduce_max_sync(0xffffffffu, __float_as_uint(max4abs(b)));
        const float amaxA = fmaxf(__uint_as_float(ra), AMAX_FLOOR);
        const float amaxB = fmaxf(__uint_as_float(rb), AMAX_FLOOR);

        y4[base] = scale4(a, FP8_MAX / amaxA);
        if (hasb) y4[base + 32] = scale4(b, FP8_MAX / amaxB);

        if (lane == 0) scale[2 * p] = amaxA / FP8_MAX;
        if (lane == 1 && hasb) scale[2 * p + 1] = amaxB / FP8_MAX;

        if (!more) break;
        p = pn; base = nbase; a = an; b = bn; hasb = hasbn;
    }
}

extern "C" void kernel_launch(void* const* d_in, const int* in_sizes, int n_in,
                              void* d_out, int out_size)
{
    const float* x = (const float*)d_in[0];
    const size_t total = (size_t)in_sizes[0];          // M * N
    const int num_groups = (int)(total / GROUP_SIZE);
    const int num_pairs = (num_groups + 1) >> 1;

    float* base = (float*)d_out;
    float* scale;
    if ((size_t)out_size >= total + (size_t)num_groups) {
        scale = base + ((size_t)out_size - (size_t)num_groups);  // tail of d_out
    } else {
        void* sp = nullptr;
        cudaGetSymbolAddress(&sp, g_scale_scratch);
        scale = (float*)sp;
    }

    // Persistent grid: 152 SMs x 8 resident CTAs (256 thr, <=32 regs via bounds)
    int grid = 152 * 8;
    const int max_useful = (num_pairs + 7) / 8;        // don't over-launch tiny inputs
    if (grid > max_useful) grid = max_useful;
    if (grid < 1) grid = 1;

    quant_fp8_group_kernel<<<grid, 256>>>(
        (const float4*)x, (float4*)base, scale, num_groups);
}

// round 13
// speedup vs baseline: 1.1451x; 1.1451x over previous
#include <cuda_runtime.h>
#include <cuda_bf16.h>
#include <cstdint>

// Per-token-group (G=128) dynamic fp8-range quantization.
// x: [M, N] fp32 (bf16-rounded values upcast by harness).
// y = clip(x * 448/amax, +-448) fp32; scale = max(amax,1e-4)/448 per group.
// d_out layout: [y (M*N) || scale (M*N/128)] fp32.
//
// FINAL (= R8, the measured optimum): flat launch, one warp per TWO groups,
// both LDG.128 front-batched (MLP_p1=2), warp abs-max via single REDUX.MAX
// on the fabs bit pattern. Probed and rejected: MLP=4 (occ/L1-queue loss),
// .cs streaming hints (neutral), persistent grid + prefetch (LSU-queue
// inversion, -10%). DRAM ~81% = mixed-stream LTS/HBM ceiling.

#define GROUP_SIZE 128
#define FP8_MAX 448.0f
#define AMAX_FLOOR 1e-4f

__device__ float g_scale_scratch[1 << 20];  // fallback, never used in practice

__device__ __forceinline__ float max4abs(float4 v) {
    return fmaxf(fmaxf(fabsf(v.x), fabsf(v.y)), fmaxf(fabsf(v.z), fabsf(v.w)));
}

__device__ __forceinline__ float4 scale4(float4 v, float s) {
    float4 o;
    o.x = fminf(fmaxf(v.x * s, -FP8_MAX), FP8_MAX);
    o.y = fminf(fmaxf(v.y * s, -FP8_MAX), FP8_MAX);
    o.z = fminf(fmaxf(v.z * s, -FP8_MAX), FP8_MAX);
    o.w = fminf(fmaxf(v.w * s, -FP8_MAX), FP8_MAX);
    return o;
}

// One warp handles TWO groups (2 x 128 fp32 = 2 x 32 float4).
// Both 16B loads issue back-to-back (MLP_p1 = 2) before any dependency.
// Warp abs-max via REDUX.MAX.U32 on the fabs bit pattern (monotone for >=0).
__global__ void __launch_bounds__(256) quant_fp8_group_kernel(
    const float4* __restrict__ x4,
    float4* __restrict__ y4,
    float* __restrict__ scale,
    int num_groups)
{
    const int warp = threadIdx.x >> 5;
    const int lane = threadIdx.x & 31;
    const int g0 = (blockIdx.x * 8 + warp) * 2;     // first of two groups
    if (g0 >= num_groups) return;

    const size_t base = (size_t)g0 * 32 + (size_t)lane;  // in float4 units

    // Front-batched independent loads (two groups)
    float4 a = x4[base];
    float4 b = x4[base + 32];

    // Per-lane abs-max, then single-instruction warp reduce per group
    unsigned ra = __reduce_max_sync(0xffffffffu, __float_as_uint(max4abs(a)));
    unsigned rb = __reduce_max_sync(0xffffffffu, __float_as_uint(max4abs(b)));

    const float amaxA = fmaxf(__uint_as_float(ra), AMAX_FLOOR);
    const float amaxB = fmaxf(__uint_as_float(rb), AMAX_FLOOR);

    y4[base]      = scale4(a, FP8_MAX / amaxA);
    y4[base + 32] = scale4(b, FP8_MAX / amaxB);

    if (lane == 0) scale[g0] = amaxA / FP8_MAX;
    if (lane == 1 && g0 + 1 < num_groups) scale[g0 + 1] = amaxB / FP8_MAX;
}

extern "C" void kernel_launch(void* const* d_in, const int* in_sizes, int n_in,
                              void* d_out, int out_size)
{
    const float* x = (const float*)d_in[0];
    const size_t total = (size_t)in_sizes[0];          // M * N
    const int num_groups = (int)(total / GROUP_SIZE);

    float* base = (float*)d_out;
    float* scale;
    if ((size_t)out_size >= total + (size_t)num_groups) {
        scale = base + ((size_t)out_size - (size_t)num_groups);  // tail of d_out
    } else {
        void* sp = nullptr;
        cudaGetSymbolAddress(&sp, g_scale_scratch);
        scale = (float*)sp;
    }

    // 8 warps/block, 2 groups/warp -> 16 groups per block
    const int groups_per_block = 16;
    const int grid = (num_groups + groups_per_block - 1) / groups_per_block;
    quant_fp8_group_kernel<<<grid, 256>>>(
        (const float4*)x, (float4*)base, scale, num_groups);
}